// round 1
// baseline (speedup 1.0000x reference)
#include <cuda_runtime.h>
#include <math.h>

// Problem constants
#define NNODES   50000
#define DISTN    8
#define P_TOT    400000          // NNODES * DISTN
#define KCB      64
#define HIDN     256
#define NGRAPH   64
#define EPSV     0.1f
#define NITER    20
#define STABV    1e-8f
#define CLMAX    1e6f
#define BMARG    (1.0f/64.0f)

// Prune threshold: exp(-cost/EPS) == 0.0f (fp32, incl. denormals) requires
// cost/EPS >= ~104. We prune only when the Cauchy-Schwarz lower bound
// (|x|-cmax)^2 >= 11.0  =>  exp arg >= 110  => exactly 0 in the reference too.
#define PRUNE_COST 11.0f

// Device scratch (allowed: __device__ globals, no cudaMalloc)
__device__ float          g_Kmat[(size_t)P_TOT * KCB];  // only rows with flag=1 are valid
__device__ unsigned char  g_flag[P_TOT];
__device__ float          g_u[P_TOT];                   // u at iteration 20 (nonzero rows only)
__device__ float          g_ynorm[KCB];
__device__ int            g_cmax_bits;
__device__ int            g_counts[NGRAPH];
__device__ int            g_is64;

// ---------------------------------------------------------------------------
__global__ void init_kernel() {
    int t = threadIdx.x;
    if (t < NGRAPH) g_counts[t] = 0;
    if (t == 0) { g_cmax_bits = 0; g_is64 = 1; }
}

// batch_idx dtype detection: if it is int64 (little-endian, values in [0,64)),
// every odd 32-bit word of the first NNODES int32s is 0. If it is int32,
// odd-index entries hold real sorted values (up to 63) -> nonzero exists.
// Only reads within min(possible) buffer size (NNODES * 4 bytes).
__global__ void detect_kernel(const int* __restrict__ b32) {
    int i = blockIdx.x * blockDim.x + threadIdx.x;
    int stride = gridDim.x * blockDim.x;
    for (; i < NNODES / 2; i += stride) {
        if (b32[2 * i + 1] != 0) g_is64 = 0;
    }
}

// Per-codebook-row squared norm + global max length (for the prune bound).
__global__ void ynorm_kernel(const float* __restrict__ cb) {
    int c = blockIdx.x;        // 64 blocks
    int t = threadIdx.x;       // 256 threads
    float v = cb[c * HIDN + t];
    float s = v * v;
    #pragma unroll
    for (int o = 16; o; o >>= 1) s += __shfl_xor_sync(~0u, s, o);
    __shared__ float red[8];
    if ((t & 31) == 0) red[t >> 5] = s;
    __syncthreads();
    if (t == 0) {
        float yn = 0.f;
        #pragma unroll
        for (int i = 0; i < 8; i++) yn += red[i];
        g_ynorm[c] = yn;
        // yn >= 0 so IEEE bits are monotonic under int compare
        atomicMax(&g_cmax_bits, __float_as_int(sqrtf(yn)));
    }
}

__global__ void counts_kernel(const void* __restrict__ bidx) {
    __shared__ int h[NGRAPH];
    int t = threadIdx.x;
    if (t < NGRAPH) h[t] = 0;
    __syncthreads();
    const int is64 = g_is64;
    const long long* b64 = (const long long*)bidx;
    const int*       b32 = (const int*)bidx;
    int i = blockIdx.x * blockDim.x + t;
    int stride = gridDim.x * blockDim.x;
    for (; i < NNODES; i += stride) {
        int g = is64 ? (int)b64[i] : b32[i];
        atomicAdd(&h[g], 1);
    }
    __syncthreads();
    if (t < NGRAPH && h[t]) atomicAdd(&g_counts[t], h[t]);
}

// ---------------------------------------------------------------------------
// Kmat: one warp per point-row. Prune via norm bound; otherwise full 64 dots.
__global__ void __launch_bounds__(256) kmat_kernel(const float* __restrict__ x,
                                                   const float* __restrict__ cb) {
    __shared__ float xs[8 * HIDN];
    const int warp = threadIdx.x >> 5;
    const int lane = threadIdx.x & 31;
    const int row  = blockIdx.x * 8 + warp;

    const float4* xr = (const float4*)(x + (size_t)row * HIDN);
    float4 a = xr[lane];        // k = [4*lane, 4*lane+4)       (coalesced)
    float4 b = xr[32 + lane];   // k = [128+4*lane, 128+4*lane+4)
    float s = a.x*a.x + a.y*a.y + a.z*a.z + a.w*a.w
            + b.x*b.x + b.y*b.y + b.z*b.z + b.w*b.w;
    #pragma unroll
    for (int o = 16; o; o >>= 1) s += __shfl_xor_sync(~0u, s, o);
    const float xn = s;

    const float cmax = __int_as_float(g_cmax_bits);
    const float xl = sqrtf(xn);
    const bool prune = (xl > cmax) && ((xl - cmax) * (xl - cmax) >= PRUNE_COST);
    if (prune) {
        if (lane == 0) g_flag[row] = 0;  // entire row is exactly 0 in fp32
        return;
    }

    // Full path (general correctness): stage x row, compute 2 codes per lane.
    float4* xsm4 = (float4*)(xs + warp * HIDN);
    xsm4[lane] = a;
    xsm4[32 + lane] = b;
    __syncwarp();

    const int c0 = lane, c1 = lane + 32;
    const float4* cb0 = (const float4*)(cb + (size_t)c0 * HIDN);
    const float4* cb1 = (const float4*)(cb + (size_t)c1 * HIDN);
    float d0 = 0.f, d1 = 0.f;
    #pragma unroll 8
    for (int t = 0; t < HIDN / 4; t++) {
        float4 xv = xsm4[t];
        float4 p = cb0[t], q = cb1[t];
        d0 += xv.x*p.x + xv.y*p.y + xv.z*p.z + xv.w*p.w;
        d1 += xv.x*q.x + xv.y*q.y + xv.z*q.z + xv.w*q.w;
    }
    float cost0 = xn + g_ynorm[c0] - 2.f * d0;
    float cost1 = xn + g_ynorm[c1] - 2.f * d1;

    // Match reference semantics: nan cost -> nan Kmat -> STAB; inf cost -> exp(-inf)=0.
    float k0, k1;
    unsigned bits0 = __float_as_uint(cost0) & 0x7fffffffu;
    unsigned bits1 = __float_as_uint(cost1) & 0x7fffffffu;
    if (bits0 > 0x7f800000u) k0 = STABV;
    else                     k0 = expf(-fmaxf(cost0, 0.f) / EPSV);
    if (bits1 > 0x7f800000u) k1 = STABV;
    else                     k1 = expf(-fmaxf(cost1, 0.f) / EPSV);

    g_Kmat[(size_t)row * KCB + c0] = k0;
    g_Kmat[(size_t)row * KCB + c1] = k1;

    unsigned nz = __ballot_sync(~0u, (k0 != 0.f) || (k1 != 0.f));
    if (lane == 0) g_flag[row] = nz ? 1 : 0;
}

// ---------------------------------------------------------------------------
// Sinkhorn is independent per graph (batch_idx sorted -> contiguous rows).
// One block per graph: 20 iterations + final wsum + normalization fused.
__global__ void __launch_bounds__(1024) sinkhorn_kernel(float* __restrict__ out) {
    __shared__ float sV[64], sKTU[64], sW[64];
    __shared__ int   sRange[2];
    __shared__ float sTot;

    const int b    = blockIdx.x;
    const int tid  = threadIdx.x;
    const int lane = tid & 31;
    const int warp = tid >> 5;        // 32 warps

    if (tid == 0) {
        int s = 0;
        for (int g = 0; g < b; g++) s += g_counts[g];
        sRange[0] = s * DISTN;
        sRange[1] = (s + g_counts[b]) * DISTN;
    }
    if (tid < 64) { sV[tid] = 1.f; sKTU[tid] = 0.f; sW[tid] = 0.f; }
    __syncthreads();

    const int rs = sRange[0], re = sRange[1];
    const float a = 1.f / fmaxf((float)(re - rs), 1.f);

    for (int iter = 0; iter < NITER; iter++) {
        float v0 = sV[lane], v1 = sV[lane + 32];
        float ktu0 = 0.f, ktu1 = 0.f;
        for (int row = rs + warp; row < re; row += 32) {
            if (!g_flag[row]) continue;   // zero row: u never multiplies a nonzero K
            float k0 = g_Kmat[(size_t)row * KCB + lane];
            float k1 = g_Kmat[(size_t)row * KCB + 32 + lane];
            float kv = k0 * v0 + k1 * v1;
            #pragma unroll
            for (int o = 16; o; o >>= 1) kv += __shfl_xor_sync(~0u, kv, o);
            float u = a / fmaxf(kv, STABV);
            if (iter == NITER - 1 && lane == 0) g_u[row] = u;
            ktu0 += k0 * u;
            ktu1 += k1 * u;
        }
        atomicAdd(&sKTU[lane], ktu0);
        atomicAdd(&sKTU[lane + 32], ktu1);
        __syncthreads();
        if (tid < 64) {
            sV[tid] = BMARG / fmaxf(sKTU[tid], STABV);
            sKTU[tid] = 0.f;
        }
        __syncthreads();
    }

    // wsum = segsum(K * clip(u)), then * clip(v), row-normalize.
    {
        float w0 = 0.f, w1 = 0.f;
        for (int row = rs + warp; row < re; row += 32) {
            if (!g_flag[row]) continue;
            float uc = fminf(fmaxf(g_u[row], STABV), CLMAX);
            float k0 = g_Kmat[(size_t)row * KCB + lane];
            float k1 = g_Kmat[(size_t)row * KCB + 32 + lane];
            w0 += k0 * uc;
            w1 += k1 * uc;
        }
        atomicAdd(&sW[lane], w0);
        atomicAdd(&sW[lane + 32], w1);
    }
    __syncthreads();
    if (tid < 64) {
        float vc = fminf(fmaxf(sV[tid], STABV), CLMAX);
        sW[tid] = sW[tid] * vc;
    }
    __syncthreads();
    if (tid < 32) {
        float t = sW[tid] + sW[tid + 32];
        #pragma unroll
        for (int o = 16; o; o >>= 1) t += __shfl_xor_sync(~0u, t, o);
        if (tid == 0) sTot = t;
    }
    __syncthreads();
    if (tid < 64) {
        float total = sTot;
        float val = (total > STABV) ? (sW[tid] / fmaxf(total, STABV)) : BMARG;
        out[b * KCB + tid] = ((re - rs) == 0) ? 0.f : val;
    }
}

// ---------------------------------------------------------------------------
extern "C" void kernel_launch(void* const* d_in, const int* in_sizes, int n_in,
                              void* d_out, int out_size) {
    const float* x    = (const float*)d_in[0];   // node_distributions [50000,8,256]
    const void*  bidx = d_in[1];                 // batch_idx [50000] int64 or int32
    const float* cb   = (const float*)d_in[2];   // codebook [64,256]
    float* out = (float*)d_out;                  // [64,64] float32

    init_kernel<<<1, 64>>>();
    detect_kernel<<<64, 256>>>((const int*)bidx);
    ynorm_kernel<<<KCB, 256>>>(cb);
    counts_kernel<<<64, 256>>>(bidx);
    kmat_kernel<<<P_TOT / 8, 256>>>(x, cb);
    sinkhorn_kernel<<<NGRAPH, 1024>>>(out);
}

// round 2
// speedup vs baseline: 13.0433x; 13.0433x over previous
#include <cuda_runtime.h>
#include <math.h>

// Problem constants
#define NNODES   50000
#define DISTN    8
#define P_TOT    400000          // NNODES * DISTN
#define KCB      64
#define HIDN     256
#define NGRAPH   64
#define EPSV     0.1f
#define NITER    20
#define STABV    1e-8f
#define CLMAX    1e6f
#define BMARG    (1.0f/64.0f)

// Prune threshold: exp(-cost/EPS) == 0.0f (fp32, incl. subnormals) requires
// cost/EPS >= ~104. We prune only when the Cauchy-Schwarz lower bound
// (|x|_prefix - cmax)^2 >= 11  =>  true cost >= 11  =>  exp arg >= 110
// => exactly 0 in the reference as well (bit-exact pruning).
#define PRUNE_COST 11.0f

// Device scratch (__device__ globals only; no allocation)
__device__ float          g_Kmat[(size_t)P_TOT * KCB];  // valid only where flag=1
__device__ unsigned char  g_flag[P_TOT];
__device__ float          g_u[P_TOT];
__device__ float          g_ynorm[KCB];
__device__ int            g_nz[NGRAPH];                 // nonzero-row count per graph
__device__ unsigned char  g_oz[64];                     // per-block "odd words all zero"

// ---------------------------------------------------------------------------
// prep: codebook row norms (block b -> row b), int64-vs-int32 detection over
// the safe range (first NNODES 32-bit words, valid under both layouts),
// and zeroing of g_nz.
__global__ void __launch_bounds__(256) prep_kernel(const float* __restrict__ cb,
                                                   const int* __restrict__ b32) {
    const int b = blockIdx.x;      // 64 blocks
    const int t = threadIdx.x;     // 256 threads

    // ---- ynorm for codebook row b ----
    float v = cb[b * HIDN + t];
    float s = v * v;
    #pragma unroll
    for (int o = 16; o; o >>= 1) s += __shfl_xor_sync(~0u, s, o);
    __shared__ float red[8];
    if ((t & 31) == 0) red[t >> 5] = s;

    // ---- detection: if batch_idx is int64 (values < 2^31), every odd 32-bit
    // word of the first NNODES words is zero. Safe-range read only. ----
    int allz = 1;
    for (int i = b * 256 + t; i < NNODES / 2; i += 64 * 256)
        if (b32[2 * i + 1] != 0) allz = 0;
    allz = __all_sync(~0u, allz);
    __shared__ int oz[8];
    if ((t & 31) == 0) oz[t >> 5] = allz;
    __syncthreads();

    if (t == 0) {
        float yn = 0.f;
        #pragma unroll
        for (int i = 0; i < 8; i++) yn += red[i];
        g_ynorm[b] = yn;
        int o = 1;
        #pragma unroll
        for (int i = 0; i < 8; i++) o &= oz[i];
        g_oz[b] = (unsigned char)o;
        g_nz[b] = 0;
    }
}

// ---------------------------------------------------------------------------
// kmat: 4 rows per warp, two-stage prefix-norm pruning.
//   stage 1: first 32 floats (one 128B line) per row  -> ~93% prune
//   stage 2: next 32 floats                           -> ~all remaining prune
//   fallback: exact full-row path (general correctness)
__global__ void __launch_bounds__(256) kmat_kernel(const float* __restrict__ x,
                                                   const float* __restrict__ cb,
                                                   const void* __restrict__ bidx) {
    __shared__ float xs[8 * HIDN];
    const int warp = threadIdx.x >> 5;
    const int lane = threadIdx.x & 31;
    const int oct  = lane >> 3;        // 4 rows per warp, 8 lanes per row
    const int ol   = lane & 7;
    const int row0 = (blockIdx.x * 8 + warp) * 4;
    const int row  = row0 + oct;

    // cmax = max_k ||c_k|| (redundant per warp; 256B, L1-resident)
    float m = fmaxf(g_ynorm[lane], g_ynorm[lane + 32]);
    #pragma unroll
    for (int o = 16; o; o >>= 1) m = fmaxf(m, __shfl_xor_sync(~0u, m, o));
    const float cmax = sqrtf(m);

    const float4* xr = (const float4*)(x + (size_t)row * HIDN);

    // stage 1: floats [0,32)
    float4 a = xr[ol];
    float ps = a.x*a.x + a.y*a.y + a.z*a.z + a.w*a.w;
    ps += __shfl_xor_sync(~0u, ps, 4);
    ps += __shfl_xor_sync(~0u, ps, 2);
    ps += __shfl_xor_sync(~0u, ps, 1);
    float d = sqrtf(ps) - cmax;
    bool prune = (d > 0.f) && (d * d >= PRUNE_COST);

    // stage 2: floats [32,64) — only for octets not yet proven
    unsigned need2 = __ballot_sync(~0u, !prune);
    if (need2) {
        const bool mine = !prune;
        float4 bb = make_float4(0.f, 0.f, 0.f, 0.f);
        if (mine) bb = xr[8 + ol];
        float p2 = bb.x*bb.x + bb.y*bb.y + bb.z*bb.z + bb.w*bb.w;
        p2 += __shfl_xor_sync(~0u, p2, 4);
        p2 += __shfl_xor_sync(~0u, p2, 2);
        p2 += __shfl_xor_sync(~0u, p2, 1);
        if (mine) {
            ps += p2;
            d = sqrtf(ps) - cmax;
            prune = (d > 0.f) && (d * d >= PRUNE_COST);
        }
    }

    if (prune && ol == 0) g_flag[row] = 0;

    unsigned needf = __ballot_sync(~0u, !prune);
    if (!needf) return;

    // ---------------- rare exact fallback ----------------
    bool ozl = (g_oz[lane] != 0) && (g_oz[lane + 32] != 0);
    const int is64 = __all_sync(~0u, ozl);

    float4* sm = (float4*)(xs + warp * HIDN);
    for (int o2 = 0; o2 < 4; o2++) {
        if (!((needf >> (o2 * 8)) & 1u)) continue;
        const int r = row0 + o2;
        const float4* xr4 = (const float4*)(x + (size_t)r * HIDN);
        float4 va = xr4[lane];
        float4 vb = xr4[32 + lane];
        float s = va.x*va.x + va.y*va.y + va.z*va.z + va.w*va.w
                + vb.x*vb.x + vb.y*vb.y + vb.z*vb.z + vb.w*vb.w;
        #pragma unroll
        for (int o = 16; o; o >>= 1) s += __shfl_xor_sync(~0u, s, o);
        const float xn = s;

        sm[lane] = va;
        sm[32 + lane] = vb;
        __syncwarp();

        const int c0 = lane, c1 = lane + 32;
        const float4* cb0 = (const float4*)(cb + (size_t)c0 * HIDN);
        const float4* cb1 = (const float4*)(cb + (size_t)c1 * HIDN);
        float d0 = 0.f, d1 = 0.f;
        #pragma unroll 8
        for (int t = 0; t < HIDN / 4; t++) {
            float4 xv = sm[t];
            float4 p = cb0[t], q = cb1[t];
            d0 += xv.x*p.x + xv.y*p.y + xv.z*p.z + xv.w*p.w;
            d1 += xv.x*q.x + xv.y*q.y + xv.z*q.z + xv.w*q.w;
        }
        float cost0 = xn + g_ynorm[c0] - 2.f * d0;
        float cost1 = xn + g_ynorm[c1] - 2.f * d1;

        // reference semantics: nan/inf Kmat -> STAB (exp(-inf)=0 stays 0)
        float k0, k1;
        unsigned bits0 = __float_as_uint(cost0) & 0x7fffffffu;
        unsigned bits1 = __float_as_uint(cost1) & 0x7fffffffu;
        if (bits0 > 0x7f800000u) k0 = STABV;
        else                     k0 = expf(-fmaxf(cost0, 0.f) / EPSV);
        if (bits1 > 0x7f800000u) k1 = STABV;
        else                     k1 = expf(-fmaxf(cost1, 0.f) / EPSV);

        g_Kmat[(size_t)r * KCB + c0] = k0;
        g_Kmat[(size_t)r * KCB + c1] = k1;

        unsigned nz = __ballot_sync(~0u, (k0 != 0.f) || (k1 != 0.f));
        if (lane == 0) {
            g_flag[r] = nz ? 1 : 0;
            if (nz) {
                const int node = r >> 3;
                int g = is64 ? (int)((const long long*)bidx)[node]
                             : ((const int*)bidx)[node];
                g = min(max(g, 0), NGRAPH - 1);
                atomicAdd(&g_nz[g], 1);
            }
        }
        __syncwarp();
    }
}

// ---------------------------------------------------------------------------
// sinkhorn: one block per graph. Builds its own node histogram (smem), then
// short-circuits when the graph has zero nonzero K rows (the common case:
// wsum == 0 -> total == 0 -> output is exactly 1/K, or 0 for empty graphs).
__global__ void __launch_bounds__(1024) sinkhorn_kernel(float* __restrict__ out,
                                                        const void* __restrict__ bidx) {
    __shared__ int   hist[NGRAPH];
    __shared__ float sV[64], sKTU[64], sW[64];
    __shared__ int   sRange[2];
    __shared__ float sTot;
    __shared__ int   sIs64;

    const int b    = blockIdx.x;
    const int tid  = threadIdx.x;
    const int lane = tid & 31;
    const int warp = tid >> 5;        // 32 warps

    if (tid < NGRAPH) hist[tid] = 0;
    if (tid == 0) {
        int o = 1;
        for (int i = 0; i < 64; i++) o &= (int)g_oz[i];
        sIs64 = o;
    }
    __syncthreads();

    const int is64 = sIs64;
    const long long* b64 = (const long long*)bidx;
    const int*       b32 = (const int*)bidx;
    for (int i = tid; i < NNODES; i += 1024) {
        int g = is64 ? (int)b64[i] : b32[i];
        g = min(max(g, 0), NGRAPH - 1);
        atomicAdd(&hist[g], 1);
    }
    __syncthreads();

    if (tid == 0) {
        int s = 0;
        for (int g = 0; g < b; g++) s += hist[g];
        sRange[0] = s * DISTN;
        sRange[1] = (s + hist[b]) * DISTN;
    }
    if (tid < 64) { sV[tid] = 1.f; sKTU[tid] = 0.f; sW[tid] = 0.f; }
    __syncthreads();

    const int rs = sRange[0], re = sRange[1];

    // Fast path: every K row of this graph is exactly zero.
    if (g_nz[b] == 0) {
        if (tid < 64) out[b * KCB + tid] = (re == rs) ? 0.f : BMARG;
        return;
    }

    // -------- general path (unchanged from the verified round-1 kernel) ----
    const float a = 1.f / fmaxf((float)(re - rs), 1.f);

    for (int iter = 0; iter < NITER; iter++) {
        float v0 = sV[lane], v1 = sV[lane + 32];
        float ktu0 = 0.f, ktu1 = 0.f;
        for (int row = rs + warp; row < re; row += 32) {
            if (!g_flag[row]) continue;
            float k0 = g_Kmat[(size_t)row * KCB + lane];
            float k1 = g_Kmat[(size_t)row * KCB + 32 + lane];
            float kv = k0 * v0 + k1 * v1;
            #pragma unroll
            for (int o = 16; o; o >>= 1) kv += __shfl_xor_sync(~0u, kv, o);
            float u = a / fmaxf(kv, STABV);
            if (iter == NITER - 1 && lane == 0) g_u[row] = u;
            ktu0 += k0 * u;
            ktu1 += k1 * u;
        }
        atomicAdd(&sKTU[lane], ktu0);
        atomicAdd(&sKTU[lane + 32], ktu1);
        __syncthreads();
        if (tid < 64) {
            sV[tid] = BMARG / fmaxf(sKTU[tid], STABV);
            sKTU[tid] = 0.f;
        }
        __syncthreads();
    }

    {
        float w0 = 0.f, w1 = 0.f;
        for (int row = rs + warp; row < re; row += 32) {
            if (!g_flag[row]) continue;
            float uc = fminf(fmaxf(g_u[row], STABV), CLMAX);
            float k0 = g_Kmat[(size_t)row * KCB + lane];
            float k1 = g_Kmat[(size_t)row * KCB + 32 + lane];
            w0 += k0 * uc;
            w1 += k1 * uc;
        }
        atomicAdd(&sW[lane], w0);
        atomicAdd(&sW[lane + 32], w1);
    }
    __syncthreads();
    if (tid < 64) {
        float vc = fminf(fmaxf(sV[tid], STABV), CLMAX);
        sW[tid] = sW[tid] * vc;
    }
    __syncthreads();
    if (tid < 32) {
        float t = sW[tid] + sW[tid + 32];
        #pragma unroll
        for (int o = 16; o; o >>= 1) t += __shfl_xor_sync(~0u, t, o);
        if (tid == 0) sTot = t;
    }
    __syncthreads();
    if (tid < 64) {
        float total = sTot;
        float val = (total > STABV) ? (sW[tid] / fmaxf(total, STABV)) : BMARG;
        out[b * KCB + tid] = ((re - rs) == 0) ? 0.f : val;
    }
}

// ---------------------------------------------------------------------------
extern "C" void kernel_launch(void* const* d_in, const int* in_sizes, int n_in,
                              void* d_out, int out_size) {
    const float* x    = (const float*)d_in[0];   // node_distributions [50000,8,256]
    const void*  bidx = d_in[1];                 // batch_idx [50000] int64 or int32
    const float* cb   = (const float*)d_in[2];   // codebook [64,256]
    float* out = (float*)d_out;                  // [64,64] float32

    prep_kernel<<<64, 256>>>(cb, (const int*)bidx);
    kmat_kernel<<<P_TOT / 32, 256>>>(x, cb, bidx);
    sinkhorn_kernel<<<NGRAPH, 1024>>>(out, bidx);
}